// round 11
// baseline (speedup 1.0000x reference)
#include <cuda_runtime.h>
#include <cuda_fp16.h>
#include <mma.h>
#include <cstdint>

using namespace nvcuda;

#define SEQ    512
#define INSZ   4096
#define HID    2048
#define OUTSZ  4096
#define STEPS  30
#define G3     6144   // 3*HID

#define NB     128    // persistent CTAs (1/SM, guaranteed co-resident)
#define NT     512    // 16 warps
#define UPB    16     // hidden units per block   (2048/128)
#define RPB    48     // gate rows per block      (3*UPB)
#define RPW    3      // rows per warp            (48/16)
#define ORPB   32     // output rows per block    (4096/128)
#define ORPW   2      // output rows per warp

// ---------------- device globals (static scratch; no runtime allocation) ----
__device__ float               g_GI[SEQ * G3];        // Wih@x (NO bias)
__device__ __half              g_Xh[SEQ * INSZ];      // fp16 input
__device__ __half              g_Wh[G3 * INSZ];       // fp16 enc_Wih
__device__ float               g_h[2][HID];           // double-buffered hidden
__device__ unsigned            g_arrive[NB];          // barrier flags (zero-init)
__device__ unsigned long long  g_pack[NB];            // (sortable lmax | revidx)
__device__ float               g_lsum[NB];            // local sumexp (rel lmax)

// ---------------- helpers ---------------------------------------------------
__device__ __forceinline__ float warp_sum(float v) {
#pragma unroll
    for (int o = 16; o; o >>= 1) v += __shfl_xor_sync(0xffffffffu, v, o);
    return v;
}
__device__ __forceinline__ float sigmoidf_(float x) {
    return 1.0f / (1.0f + expf(-x));
}
__device__ __forceinline__ unsigned f2sortable(float v) {
    unsigned sb = __float_as_uint(v);
    return (sb & 0x80000000u) ? ~sb : (sb | 0x80000000u);
}
__device__ __forceinline__ float sortable2f(unsigned s) {
    return __uint_as_float((s & 0x80000000u) ? (s & 0x7FFFFFFFu) : ~s);
}

// Grid barrier, cooperative-groups style: one release fence + relaxed flag
// store by thread 0; warp 0 polls all 128 flags with v4 relaxed loads; one
// acquire fence; __syncthreads propagates ordering to the whole CTA.
// Monotonic counters survive graph replays (flags equal at launch start,
// base captured from own flag before any store).
__device__ __forceinline__ void grid_bar(int bid, unsigned base, unsigned* kbar) {
    unsigned k = ++(*kbar);
    __syncthreads();                        // CTA work done; CTA-scope visible
    if (threadIdx.x == 0) {
        asm volatile("fence.acq_rel.gpu;" ::: "memory");
        asm volatile("st.relaxed.gpu.global.u32 [%0], %1;"
                     :: "l"(&g_arrive[bid]), "r"(base + k) : "memory");
    }
    if (threadIdx.x < 32) {
        const uint4* fp = (const uint4*)g_arrive + threadIdx.x;
        for (;;) {
            unsigned a, b, c, d;
            asm volatile("ld.relaxed.gpu.global.v4.u32 {%0,%1,%2,%3}, [%4];"
                         : "=r"(a), "=r"(b), "=r"(c), "=r"(d)
                         : "l"(fp) : "memory");
            unsigned mn = min(min(a - base, b - base), min(c - base, d - base));
            if (__all_sync(0xffffffffu, mn >= k)) break;
        }
        asm volatile("fence.acq_rel.gpu;" ::: "memory");
    }
    __syncthreads();
}

// Load hidden state (fp32 global, other SMs' writes) -> SMEM as half2.
__device__ __forceinline__ void load_h_h2(const float* hsrc, __half2* hp, int tid) {
    float4 a = __ldcg((const float4*)(hsrc + tid * 4));
    uint2 u;
    *(__half2*)&u.x = __floats2half2_rn(a.x, a.y);
    *(__half2*)&u.y = __floats2half2_rn(a.z, a.w);
    *(uint2*)(hp + tid * 2) = u;
}
__device__ __forceinline__ void load_h_f32(const float* hsrc, float* hs, int tid) {
    float4 v = __ldcg((const float4*)(hsrc + tid * 4));
    *(float4*)&hs[tid * 4] = v;
}

// One-time: this CTA's 48 Whh rows (fp32, global) -> SMEM fp16.
__device__ void load_w48(const float* __restrict__ W, __half* ws, int bid, int tid) {
    int warp = tid >> 5, lane = tid & 31;
#pragma unroll
    for (int rr = 0; rr < RPW; rr++) {
        int r48  = warp * RPW + rr;
        int grow = (r48 >> 4) * HID + bid * UPB + (r48 & 15);
        const float4* src = (const float4*)(W + (size_t)grow * HID);
#pragma unroll
        for (int c = 0; c < 16; c++) {
            float4 v = __ldg(&src[lane + c * 32]);
            union { __half2 h[2]; uint2 u; } cv;
            cv.h[0] = __floats2half2_rn(v.x, v.y);
            cv.h[1] = __floats2half2_rn(v.z, v.w);
            *(uint2*)&ws[(size_t)r48 * HID + (lane + c * 32) * 4] = cv.u;
        }
    }
}

// 48-row x 2048 matvec, fp16 weights+h in SMEM, HFMA2 with fp32 flush / 16.
__device__ __forceinline__ void matvec48_h2(const __half* __restrict__ ws,
                                            const __half2* __restrict__ hp,
                                            float* gh_s, const float* bhh_s,
                                            int tid) {
    int warp = tid >> 5, lane = tid & 31;
    float acc[RPW] = {0.f, 0.f, 0.f};
#pragma unroll
    for (int c = 0; c < 8; c += 2) {
        int g0 = (c * 32 + lane) * 4;          // half2 index
        int g1 = ((c + 1) * 32 + lane) * 4;
        uint4 hu0 = *(const uint4*)(hp + g0);
        uint4 hu1 = *(const uint4*)(hp + g1);
        __half2 h0 = *(__half2*)&hu0.x, h1 = *(__half2*)&hu0.y;
        __half2 h2 = *(__half2*)&hu0.z, h3 = *(__half2*)&hu0.w;
        __half2 h4 = *(__half2*)&hu1.x, h5 = *(__half2*)&hu1.y;
        __half2 h6 = *(__half2*)&hu1.z, h7 = *(__half2*)&hu1.w;
#pragma unroll
        for (int rr = 0; rr < RPW; rr++) {
            const __half2* wrow =
                (const __half2*)(ws + (size_t)(warp * RPW + rr) * HID);
            uint4 w0 = *(const uint4*)(wrow + g0);
            uint4 w1 = *(const uint4*)(wrow + g1);
            __half2 s = __hmul2(*(__half2*)&w0.x, h0);
            s = __hfma2(*(__half2*)&w0.y, h1, s);
            s = __hfma2(*(__half2*)&w0.z, h2, s);
            s = __hfma2(*(__half2*)&w0.w, h3, s);
            s = __hfma2(*(__half2*)&w1.x, h4, s);
            s = __hfma2(*(__half2*)&w1.y, h5, s);
            s = __hfma2(*(__half2*)&w1.z, h6, s);
            s = __hfma2(*(__half2*)&w1.w, h7, s);
            float2 f = __half22float2(s);
            acc[rr] += f.x + f.y;
        }
    }
#pragma unroll
    for (int rr = 0; rr < RPW; rr++) {
        float s = warp_sum(acc[rr]);
        if (lane == 0) gh_s[warp * RPW + rr] = s + bhh_s[warp * RPW + rr];
    }
}

// ---------------- fp32 -> fp16 converters -----------------------------------
__global__ void __launch_bounds__(256) conv_x_kernel(const float* __restrict__ src) {
    int i = blockIdx.x * blockDim.x + threadIdx.x;   // float4 index
    if (i < SEQ * INSZ / 4) {
        float4 v = __ldg((const float4*)src + i);
        union { __half2 h[2]; uint2 u; } cv;
        cv.h[0] = __floats2half2_rn(v.x, v.y);
        cv.h[1] = __floats2half2_rn(v.z, v.w);
        ((uint2*)g_Xh)[i] = cv.u;
    }
}
__global__ void __launch_bounds__(256) conv_w_kernel(const float* __restrict__ src) {
    int i = blockIdx.x * blockDim.x + threadIdx.x;
    if (i < G3 * INSZ / 4) {
        float4 v = __ldg((const float4*)src + i);
        union { __half2 h[2]; uint2 u; } cv;
        cv.h[0] = __floats2half2_rn(v.x, v.y);
        cv.h[1] = __floats2half2_rn(v.z, v.w);
        ((uint2*)g_Wh)[i] = cv.u;
    }
}

// ---------------- kernel 1: GI = X @ Wih^T (tensor cores, fp32 accum) -------
#define KC 32
__global__ void __launch_bounds__(256) gemm_wmma_kernel() {
    __shared__ __half As[128][KC + 8];
    __shared__ __half Bs[128][KC + 8];

    int m0 = blockIdx.y * 128, n0 = blockIdx.x * 128;
    int t = threadIdx.x;
    int wid = t >> 5;
    int wm = wid & 1, wn = wid >> 1;     // warp tile: 64(M) x 32(N)

    wmma::fragment<wmma::accumulator, 16, 16, 16, float> c[4][2];
#pragma unroll
    for (int i = 0; i < 4; i++)
#pragma unroll
        for (int j = 0; j < 2; j++) wmma::fill_fragment(c[i][j], 0.f);

    int lrow = t >> 1;
    int lseg = (t & 1) * 16;

    for (int k0 = 0; k0 < INSZ; k0 += KC) {
        const uint4* ap = (const uint4*)(g_Xh + (size_t)(m0 + lrow) * INSZ + k0 + lseg);
        const uint4* bp = (const uint4*)(g_Wh + (size_t)(n0 + lrow) * INSZ + k0 + lseg);
        uint4 a0 = ap[0], a1 = ap[1];
        uint4 b0 = bp[0], b1 = bp[1];
        __syncthreads();
        *(uint4*)&As[lrow][lseg]     = a0;
        *(uint4*)&As[lrow][lseg + 8] = a1;
        *(uint4*)&Bs[lrow][lseg]     = b0;
        *(uint4*)&Bs[lrow][lseg + 8] = b1;
        __syncthreads();
#pragma unroll
        for (int kk = 0; kk < KC; kk += 16) {
            wmma::fragment<wmma::matrix_a, 16, 16, 16, __half, wmma::row_major> af[4];
            wmma::fragment<wmma::matrix_b, 16, 16, 16, __half, wmma::col_major> bf[2];
#pragma unroll
            for (int i = 0; i < 4; i++)
                wmma::load_matrix_sync(af[i], &As[wm * 64 + i * 16][kk], KC + 8);
#pragma unroll
            for (int j = 0; j < 2; j++)
                wmma::load_matrix_sync(bf[j], &Bs[wn * 32 + j * 16][kk], KC + 8);
#pragma unroll
            for (int i = 0; i < 4; i++)
#pragma unroll
                for (int j = 0; j < 2; j++)
                    wmma::mma_sync(c[i][j], af[i], bf[j], c[i][j]);
        }
    }
#pragma unroll
    for (int i = 0; i < 4; i++)
#pragma unroll
        for (int j = 0; j < 2; j++)
            wmma::store_matrix_sync(
                &g_GI[(size_t)(m0 + wm * 64 + i * 16) * G3 + n0 + wn * 32 + j * 16],
                c[i][j], G3, wmma::mem_row_major);
}

// ---------------- kernel 2: persistent encoder + decoder --------------------
__global__ void __launch_bounds__(NT, 1) rnn_kernel(
    const float* __restrict__ enc_Whh, const float* __restrict__ enc_bih,
    const float* __restrict__ enc_bhh,
    const float* __restrict__ dec_Wih, const float* __restrict__ dec_Whh,
    const float* __restrict__ dec_bih, const float* __restrict__ dec_bhh,
    const float* __restrict__ W_out,   const float* __restrict__ b_out,
    float* __restrict__ out) {

    extern __shared__ char dyn[];
    __half*  ws   = (__half*)dyn;                       // 48*2048 fp16 = 192KB
    __half2* hph2 = (__half2*)(dyn + RPB * HID * sizeof(__half));       // 4KB
    float*   hs32 = (float*)(dyn + RPB * HID * sizeof(__half)
                                 + HID * sizeof(__half));               // 8KB

    __shared__ float gh_s[RPB];
    __shared__ float gi_s[RPB];
    __shared__ float bhh_s[RPB];
    __shared__ float bih_s[RPB];
    __shared__ float ls[ORPB];
    __shared__ float red_s[3];          // gmax, gsum, idx-as-bits

    int bid = blockIdx.x, tid = threadIdx.x;
    unsigned base;
    asm volatile("ld.relaxed.gpu.global.u32 %0, [%1];"
                 : "=r"(base) : "l"(&g_arrive[bid]) : "memory");
    unsigned kbar = 0;

    // one-time: encoder Whh slice -> SMEM fp16; biases -> SMEM
    load_w48(enc_Whh, ws, bid, tid);
    if (tid < RPB) {
        int grow = (tid >> 4) * HID + bid * UPB + (tid & 15);
        bhh_s[tid] = enc_bhh[grow];
        bih_s[tid] = enc_bih[grow];
    }
    if (tid < UPB) __stcg(&g_h[0][bid * UPB + tid], 0.f);
    grid_bar(bid, base, &kbar);

    int cur = 0;

    // ---------------- encoder: 512 sequential GRU steps ----------------
    for (int t = 0; t < SEQ; t++) {
        // prefetch gi (independent of h) + hprev; consumed after matvec
        float p_gi0 = 0.f, p_gi1 = 0.f, p_gi2 = 0.f, p_hprev = 0.f;
        if (tid < UPB) {
            int u = bid * UPB + tid;
            const float* gi = g_GI + (size_t)t * G3;
            p_gi0 = __ldcg(&gi[u]);
            p_gi1 = __ldcg(&gi[HID + u]);
            p_gi2 = __ldcg(&gi[2 * HID + u]);
            p_hprev = __ldcg(&g_h[cur][u]);
        }
        load_h_h2(g_h[cur], hph2, tid);
        __syncthreads();
        matvec48_h2(ws, hph2, gh_s, bhh_s, tid);
        __syncthreads();
        if (tid < UPB) {
            int u = bid * UPB + tid;
            float r = sigmoidf_(p_gi0 + bih_s[tid]           + gh_s[tid]);
            float z = sigmoidf_(p_gi1 + bih_s[UPB + tid]     + gh_s[UPB + tid]);
            float n = tanhf(    p_gi2 + bih_s[2 * UPB + tid]
                                      + r * gh_s[2 * UPB + tid]);
            __stcg(&g_h[cur ^ 1][u], (1.f - z) * n + z * p_hprev);
        }
        cur ^= 1;
        grid_bar(bid, base, &kbar);
    }

    // ---------------- decoder: swap SMEM weights to dec_Whh ----------------
    load_w48(dec_Whh, ws, bid, tid);
    if (tid < RPB) {
        int grow = (tid >> 4) * HID + bid * UPB + (tid & 15);
        bhh_s[tid] = dec_bhh[grow];
    }
    __syncthreads();

    int prev_idx = -1;     // first x is the zero vector
    for (int s = 0; s < STEPS; s++) {
        // prefetch: one-hot Wih column + bih, and hprev
        float p_hprev = 0.f;
        if (tid < RPB) {
            int grow = (tid >> 4) * HID + bid * UPB + (tid & 15);
            float v = dec_bih[grow];
            if (prev_idx >= 0) v += __ldg(&dec_Wih[(size_t)grow * INSZ + prev_idx]);
            gi_s[tid] = v;
        }
        if (tid < UPB) p_hprev = __ldcg(&g_h[cur][bid * UPB + tid]);
        load_h_h2(g_h[cur], hph2, tid);
        __syncthreads();
        matvec48_h2(ws, hph2, gh_s, bhh_s, tid);
        __syncthreads();
        if (tid < UPB) {
            int u = bid * UPB + tid;
            float r = sigmoidf_(gi_s[tid]           + gh_s[tid]);
            float z = sigmoidf_(gi_s[UPB + tid]     + gh_s[UPB + tid]);
            float n = tanhf(    gi_s[2 * UPB + tid] + r * gh_s[2 * UPB + tid]);
            __stcg(&g_h[cur ^ 1][u], (1.f - z) * n + z * p_hprev);
        }
        cur ^= 1;
        grid_bar(bid, base, &kbar);           // B1: h_new visible everywhere

        // logits for this CTA's 32 output rows (fp32, streamed from L2)
        load_h_f32(g_h[cur], hs32, tid);
        __syncthreads();
        {
            int warp = tid >> 5, lane = tid & 31;
#pragma unroll
            for (int rr = 0; rr < ORPW; rr++) {
                int rl = warp * ORPW + rr;
                int grow = bid * ORPB + rl;
                const float4* wrow = (const float4*)(W_out + (size_t)grow * HID);
                float acc = 0.f;
#pragma unroll
                for (int kk = 0; kk < 16; kk++) {
                    float4 w4 = __ldg(&wrow[lane + kk * 32]);
                    const float4 h4 = *(const float4*)&hs32[(lane + kk * 32) * 4];
                    acc += w4.x * h4.x + w4.y * h4.y + w4.z * h4.z + w4.w * h4.w;
                }
                acc = warp_sum(acc);
                if (lane == 0) ls[rl] = acc + b_out[grow];
            }
        }
        __syncthreads();

        // publish local (max,argmax) pack + local sumexp (rel local max)
        if (tid < 32) {
            float v = ls[tid];
            unsigned long long pack =
                ((unsigned long long)f2sortable(v) << 32) |
                (unsigned long long)(0xFFFFFFFFu - (unsigned)(bid * ORPB + tid));
#pragma unroll
            for (int o = 16; o; o >>= 1) {
                unsigned long long other = __shfl_xor_sync(0xffffffffu, pack, o);
                pack = other > pack ? other : pack;
            }
            float lmax = sortable2f((unsigned)(pack >> 32));
            float e = expf(v - lmax);
            e = warp_sum(e);
            if (tid == 0) {
                __stcg(&g_pack[bid], pack);
                __stcg(&g_lsum[bid], e);
            }
        }
        grid_bar(bid, base, &kbar);           // B2: all packs/lsums visible

        // every CTA reduces the 128 (pack, lsum) pairs itself
        if (tid < 32) {
            unsigned long long pk[4];
            float lsm[4];
#pragma unroll
            for (int i = 0; i < 4; i++) {
                pk[i]  = __ldcg(&g_pack[tid + i * 32]);
                lsm[i] = __ldcg(&g_lsum[tid + i * 32]);
            }
            unsigned long long m = pk[0];
#pragma unroll
            for (int i = 1; i < 4; i++) m = pk[i] > m ? pk[i] : m;
#pragma unroll
            for (int o = 16; o; o >>= 1) {
                unsigned long long other = __shfl_xor_sync(0xffffffffu, m, o);
                m = other > m ? other : m;
            }
            float gmax = sortable2f((unsigned)(m >> 32));
            float part = 0.f;
#pragma unroll
            for (int i = 0; i < 4; i++)
                part += lsm[i] * expf(sortable2f((unsigned)(pk[i] >> 32)) - gmax);
            part = warp_sum(part);
            if (tid == 0) {
                red_s[0] = gmax;
                red_s[1] = logf(part);
                red_s[2] = __uint_as_float(0xFFFFFFFFu - (unsigned)(m & 0xFFFFFFFFull));
            }
        }
        __syncthreads();
        float gmax = red_s[0], lse = red_s[1];
        prev_idx = (int)__float_as_uint(red_s[2]);
        if (tid < 32)
            out[(size_t)s * OUTSZ + bid * ORPB + tid] = ls[tid] - gmax - lse;
    }
}

// ---------------- launch ----------------------------------------------------
extern "C" void kernel_launch(void* const* d_in, const int* in_sizes, int n_in,
                              void* d_out, int out_size) {
    const float* input   = (const float*)d_in[0];
    const float* enc_Wih = (const float*)d_in[1];
    const float* enc_Whh = (const float*)d_in[2];
    const float* enc_bih = (const float*)d_in[3];
    const float* enc_bhh = (const float*)d_in[4];
    const float* dec_Wih = (const float*)d_in[5];
    const float* dec_Whh = (const float*)d_in[6];
    const float* dec_bih = (const float*)d_in[7];
    const float* dec_bhh = (const float*)d_in[8];
    const float* W_out   = (const float*)d_in[9];
    const float* b_out   = (const float*)d_in[10];
    float* out = (float*)d_out;

    static const int kDynSmem = RPB * HID * sizeof(__half)      // weights 192KB
                              + HID * sizeof(__half)            // h fp16   4KB
                              + HID * sizeof(float);            // h fp32   8KB
    cudaFuncSetAttribute(rnn_kernel,
                         cudaFuncAttributeMaxDynamicSharedMemorySize, kDynSmem);

    conv_x_kernel<<<(SEQ * INSZ / 4 + 255) / 256, 256>>>(input);
    conv_w_kernel<<<(G3 * INSZ / 4 + 255) / 256, 256>>>(enc_Wih);

    dim3 g1(G3 / 128, SEQ / 128);   // 48 x 4
    gemm_wmma_kernel<<<g1, 256>>>();

    rnn_kernel<<<NB, NT, kDynSmem>>>(enc_Whh, enc_bih, enc_bhh,
                                     dec_Wih, dec_Whh, dec_bih, dec_bhh,
                                     W_out, b_out, out);
}

// round 12
// speedup vs baseline: 1.7739x; 1.7739x over previous
#include <cuda_runtime.h>
#include <cuda_fp16.h>
#include <mma.h>
#include <cstdint>

using namespace nvcuda;

#define SEQ    512
#define INSZ   4096
#define HID    2048
#define OUTSZ  4096
#define STEPS  30
#define G3     6144   // 3*HID

#define NB     128    // persistent CTAs (1/SM, guaranteed co-resident)
#define NT     512    // 16 warps
#define UPB    16     // hidden units per block   (2048/128)
#define RPB    48     // gate rows per block      (3*UPB)
#define RPW    3      // rows per warp            (48/16)
#define ORPB   32     // output rows per block    (4096/128)

// ---------------- device globals (static scratch; no runtime allocation) ----
__device__ float               g_GI[SEQ * G3];        // Wih@x (NO bias)
__device__ __half              g_Xh[SEQ * INSZ];      // fp16 input
__device__ __half              g_Wh[G3 * INSZ];       // fp16 enc_Wih
__device__ __half              g_Woh[OUTSZ * HID];    // fp16 W_out
__device__ float               g_hdat[2][NB][16];     // h slots (64B per CTA)
__device__ unsigned            g_flagp[NB * 8];       // h flags, 32B padded
__device__ ulonglong2          g_pdat[2][NB];         // (pack, lsum-bits) slots
__device__ unsigned            g_flag2p[NB * 8];      // pack flags, 32B padded

// ---------------- helpers ---------------------------------------------------
__device__ __forceinline__ float warp_sum(float v) {
#pragma unroll
    for (int o = 16; o; o >>= 1) v += __shfl_xor_sync(0xffffffffu, v, o);
    return v;
}
__device__ __forceinline__ float sigmoidf_(float x) {
    return 1.0f / (1.0f + expf(-x));
}
__device__ __forceinline__ unsigned f2sortable(float v) {
    unsigned sb = __float_as_uint(v);
    return (sb & 0x80000000u) ? ~sb : (sb | 0x80000000u);
}
__device__ __forceinline__ float sortable2f(unsigned s) {
    return __uint_as_float((s & 0x80000000u) ? (s & 0x7FFFFFFFu) : ~s);
}
__device__ __forceinline__ unsigned ld_flag(const unsigned* p) {
    unsigned f;
    asm volatile("ld.relaxed.gpu.global.u32 %0, [%1];" : "=r"(f) : "l"(p) : "memory");
    return f;
}
__device__ __forceinline__ void st_flag(unsigned* p, unsigned v) {
    asm volatile("st.relaxed.gpu.global.u32 [%0], %1;" :: "l"(p), "r"(v) : "memory");
}
__device__ __forceinline__ void fence_gpu() {
    asm volatile("fence.acq_rel.gpu;" ::: "memory");
}

// Publish this CTA's 16 h values for index jt (buffer jt&1) + release flag.
// Called by ALL 32 lanes of warp 0; lanes 0-15 carry hval.
__device__ __forceinline__ void publish_h(int bid, int tid, float hval,
                                          unsigned base, unsigned jt) {
    if (tid < UPB) __stcg(&g_hdat[jt & 1][bid][tid], hval);
    __syncwarp();
    if (tid == 0) {
        fence_gpu();
        st_flag(&g_flagp[bid * 8], base + jt);
    }
}

// Each warp waits for its 8 slots' flags >= jt, then loads 512B of h,
// converts to half2, stores into hdst (SMEM buffer for jt&1).
__device__ __forceinline__ void exch_load_h(int warp, int lane, unsigned base,
                                            unsigned jt, __half2* hdst) {
    if (lane < 8) {
        const unsigned* fp = &g_flagp[(warp * 8 + lane) * 8];
        while (ld_flag(fp) - base < jt) { }
    }
    __syncwarp();
    fence_gpu();
    int slot = warp * 8 + (lane >> 2);
    float4 v = __ldcg((const float4*)&g_hdat[jt & 1][slot][(lane & 3) * 4]);
    uint2 u;
    *(__half2*)&u.x = __floats2half2_rn(v.x, v.y);
    *(__half2*)&u.y = __floats2half2_rn(v.z, v.w);
    *(uint2*)(hdst + slot * 8 + (lane & 3) * 2) = u;
}

// One-time: this CTA's 48 Whh rows (fp32, global) -> SMEM fp16.
__device__ void load_w48(const float* __restrict__ W, __half* ws, int bid, int tid) {
    int warp = tid >> 5, lane = tid & 31;
#pragma unroll
    for (int rr = 0; rr < RPW; rr++) {
        int r48  = warp * RPW + rr;
        int grow = (r48 >> 4) * HID + bid * UPB + (r48 & 15);
        const float4* src = (const float4*)(W + (size_t)grow * HID);
#pragma unroll
        for (int c = 0; c < 16; c++) {
            float4 v = __ldg(&src[lane + c * 32]);
            union { __half2 h[2]; uint2 u; } cv;
            cv.h[0] = __floats2half2_rn(v.x, v.y);
            cv.h[1] = __floats2half2_rn(v.z, v.w);
            *(uint2*)&ws[(size_t)r48 * HID + (lane + c * 32) * 4] = cv.u;
        }
    }
}

// 48-row x 2048 matvec, fp16 weights+h in SMEM, HFMA2 with fp32 flush / 16.
__device__ __forceinline__ void matvec48_h2(const __half* __restrict__ ws,
                                            const __half2* __restrict__ hp,
                                            float* gh_s, const float* bhh_s,
                                            int tid) {
    int warp = tid >> 5, lane = tid & 31;
    float acc[RPW] = {0.f, 0.f, 0.f};
#pragma unroll
    for (int c = 0; c < 8; c += 2) {
        int g0 = (c * 32 + lane) * 4;          // half2 index
        int g1 = ((c + 1) * 32 + lane) * 4;
        uint4 hu0 = *(const uint4*)(hp + g0);
        uint4 hu1 = *(const uint4*)(hp + g1);
        __half2 h0 = *(__half2*)&hu0.x, h1 = *(__half2*)&hu0.y;
        __half2 h2 = *(__half2*)&hu0.z, h3 = *(__half2*)&hu0.w;
        __half2 h4 = *(__half2*)&hu1.x, h5 = *(__half2*)&hu1.y;
        __half2 h6 = *(__half2*)&hu1.z, h7 = *(__half2*)&hu1.w;
#pragma unroll
        for (int rr = 0; rr < RPW; rr++) {
            const __half2* wrow =
                (const __half2*)(ws + (size_t)(warp * RPW + rr) * HID);
            uint4 w0 = *(const uint4*)(wrow + g0);
            uint4 w1 = *(const uint4*)(wrow + g1);
            __half2 s = __hmul2(*(__half2*)&w0.x, h0);
            s = __hfma2(*(__half2*)&w0.y, h1, s);
            s = __hfma2(*(__half2*)&w0.z, h2, s);
            s = __hfma2(*(__half2*)&w0.w, h3, s);
            s = __hfma2(*(__half2*)&w1.x, h4, s);
            s = __hfma2(*(__half2*)&w1.y, h5, s);
            s = __hfma2(*(__half2*)&w1.z, h6, s);
            s = __hfma2(*(__half2*)&w1.w, h7, s);
            float2 f = __half22float2(s);
            acc[rr] += f.x + f.y;
        }
    }
#pragma unroll
    for (int rr = 0; rr < RPW; rr++) {
        float s = warp_sum(acc[rr]);
        if (lane == 0) gh_s[warp * RPW + rr] = s + bhh_s[warp * RPW + rr];
    }
}

// ---------------- fp32 -> fp16 converters -----------------------------------
__global__ void __launch_bounds__(256) conv_x_kernel(const float* __restrict__ src) {
    int i = blockIdx.x * blockDim.x + threadIdx.x;   // float4 index
    if (i < SEQ * INSZ / 4) {
        float4 v = __ldg((const float4*)src + i);
        union { __half2 h[2]; uint2 u; } cv;
        cv.h[0] = __floats2half2_rn(v.x, v.y);
        cv.h[1] = __floats2half2_rn(v.z, v.w);
        ((uint2*)g_Xh)[i] = cv.u;
    }
}
__global__ void __launch_bounds__(256) conv_w_kernel(const float* __restrict__ src) {
    int i = blockIdx.x * blockDim.x + threadIdx.x;
    if (i < G3 * INSZ / 4) {
        float4 v = __ldg((const float4*)src + i);
        union { __half2 h[2]; uint2 u; } cv;
        cv.h[0] = __floats2half2_rn(v.x, v.y);
        cv.h[1] = __floats2half2_rn(v.z, v.w);
        ((uint2*)g_Wh)[i] = cv.u;
    }
}
__global__ void __launch_bounds__(256) conv_wout_kernel(const float* __restrict__ src) {
    int i = blockIdx.x * blockDim.x + threadIdx.x;
    if (i < OUTSZ * HID / 4) {
        float4 v = __ldg((const float4*)src + i);
        union { __half2 h[2]; uint2 u; } cv;
        cv.h[0] = __floats2half2_rn(v.x, v.y);
        cv.h[1] = __floats2half2_rn(v.z, v.w);
        ((uint2*)g_Woh)[i] = cv.u;
    }
}

// ---------------- kernel 1: GI = X @ Wih^T (tensor cores, fp32 accum) -------
#define KC 32
__global__ void __launch_bounds__(256) gemm_wmma_kernel() {
    __shared__ __half As[128][KC + 8];
    __shared__ __half Bs[128][KC + 8];

    int m0 = blockIdx.y * 128, n0 = blockIdx.x * 128;
    int t = threadIdx.x;
    int wid = t >> 5;
    int wm = wid & 1, wn = wid >> 1;     // warp tile: 64(M) x 32(N)

    wmma::fragment<wmma::accumulator, 16, 16, 16, float> c[4][2];
#pragma unroll
    for (int i = 0; i < 4; i++)
#pragma unroll
        for (int j = 0; j < 2; j++) wmma::fill_fragment(c[i][j], 0.f);

    int lrow = t >> 1;
    int lseg = (t & 1) * 16;

    for (int k0 = 0; k0 < INSZ; k0 += KC) {
        const uint4* ap = (const uint4*)(g_Xh + (size_t)(m0 + lrow) * INSZ + k0 + lseg);
        const uint4* bp = (const uint4*)(g_Wh + (size_t)(n0 + lrow) * INSZ + k0 + lseg);
        uint4 a0 = ap[0], a1 = ap[1];
        uint4 b0 = bp[0], b1 = bp[1];
        __syncthreads();
        *(uint4*)&As[lrow][lseg]     = a0;
        *(uint4*)&As[lrow][lseg + 8] = a1;
        *(uint4*)&Bs[lrow][lseg]     = b0;
        *(uint4*)&Bs[lrow][lseg + 8] = b1;
        __syncthreads();
#pragma unroll
        for (int kk = 0; kk < KC; kk += 16) {
            wmma::fragment<wmma::matrix_a, 16, 16, 16, __half, wmma::row_major> af[4];
            wmma::fragment<wmma::matrix_b, 16, 16, 16, __half, wmma::col_major> bf[2];
#pragma unroll
            for (int i = 0; i < 4; i++)
                wmma::load_matrix_sync(af[i], &As[wm * 64 + i * 16][kk], KC + 8);
#pragma unroll
            for (int j = 0; j < 2; j++)
                wmma::load_matrix_sync(bf[j], &Bs[wn * 32 + j * 16][kk], KC + 8);
#pragma unroll
            for (int i = 0; i < 4; i++)
#pragma unroll
                for (int j = 0; j < 2; j++)
                    wmma::mma_sync(c[i][j], af[i], bf[j], c[i][j]);
        }
    }
#pragma unroll
    for (int i = 0; i < 4; i++)
#pragma unroll
        for (int j = 0; j < 2; j++)
            wmma::store_matrix_sync(
                &g_GI[(size_t)(m0 + wm * 64 + i * 16) * G3 + n0 + wn * 32 + j * 16],
                c[i][j], G3, wmma::mem_row_major);
}

// ---------------- kernel 2: persistent encoder + decoder --------------------
__global__ void __launch_bounds__(NT, 1) rnn_kernel(
    const float* __restrict__ enc_Whh, const float* __restrict__ enc_bih,
    const float* __restrict__ enc_bhh,
    const float* __restrict__ dec_Wih, const float* __restrict__ dec_Whh,
    const float* __restrict__ dec_bih, const float* __restrict__ dec_bhh,
    const float* __restrict__ b_out,
    float* __restrict__ out) {

    extern __shared__ char dyn[];
    __half*  ws   = (__half*)dyn;                        // 48*2048 fp16 = 192KB
    __half2* hph2 = (__half2*)(dyn + RPB * HID * sizeof(__half)); // 2x1024 h2 = 8KB

    __shared__ float gh_s[RPB];
    __shared__ float gi_s[RPB];
    __shared__ float bhh_s[RPB];
    __shared__ float bih_s[RPB];
    __shared__ float ls[ORPB];
    __shared__ float red_s[3];          // gmax, lse, idx-as-bits

    int bid = blockIdx.x, tid = threadIdx.x;
    int warp = tid >> 5, lane = tid & 31;
    unsigned base  = ld_flag(&g_flagp[bid * 8]);    // stable at launch start
    unsigned base2 = ld_flag(&g_flag2p[bid * 8]);

    // one-time: encoder Whh slice -> SMEM fp16; biases -> SMEM
    load_w48(enc_Whh, ws, bid, tid);
    if (tid < RPB) {
        int grow = (tid >> 4) * HID + bid * UPB + (tid & 15);
        bhh_s[tid] = enc_bhh[grow];
        bih_s[tid] = enc_bih[grow];
    }

    float h_reg = 0.f;                  // this thread's hidden unit (tid<16)
    unsigned j = 1;                     // publication index

    // publish initial h (zeros) as j=1, everyone load it
    if (warp == 0) publish_h(bid, tid, 0.f, base, j);
    exch_load_h(warp, lane, base, j, hph2 + (j & 1) * (HID / 2));
    __syncthreads();

    // ---------------- encoder: 512 sequential GRU steps ----------------
    for (int t = 0; t < SEQ; t++) {
        float p_gi0 = 0.f, p_gi1 = 0.f, p_gi2 = 0.f;
        if (tid < UPB) {                // prefetch gi, consumed after matvec
            int u = bid * UPB + tid;
            const float* gi = g_GI + (size_t)t * G3;
            p_gi0 = __ldcg(&gi[u]);
            p_gi1 = __ldcg(&gi[HID + u]);
            p_gi2 = __ldcg(&gi[2 * HID + u]);
        }
        matvec48_h2(ws, hph2 + (j & 1) * (HID / 2), gh_s, bhh_s, tid);
        __syncthreads();                // gh_s ready; hph2[j&1] free
        if (warp == 0) {
            if (tid < UPB) {
                float r = sigmoidf_(p_gi0 + bih_s[tid]           + gh_s[tid]);
                float z = sigmoidf_(p_gi1 + bih_s[UPB + tid]     + gh_s[UPB + tid]);
                float n = tanhf(    p_gi2 + bih_s[2 * UPB + tid]
                                          + r * gh_s[2 * UPB + tid]);
                h_reg = (1.f - z) * n + z * h_reg;
            }
            publish_h(bid, tid, h_reg, base, j + 1);
        }
        exch_load_h(warp, lane, base, j + 1, hph2 + ((j + 1) & 1) * (HID / 2));
        j++;
        __syncthreads();                // next h in SMEM; gh_s consumed
    }

    // ---------------- decoder: swap SMEM weights to dec_Whh ----------------
    load_w48(dec_Whh, ws, bid, tid);
    if (tid < RPB) {
        int grow = (tid >> 4) * HID + bid * UPB + (tid & 15);
        bhh_s[tid] = dec_bhh[grow];
    }
    __syncthreads();

    int prev_idx = -1;     // first x is the zero vector
    for (int s = 0; s < STEPS; s++) {
        if (tid < RPB) {                // gi = Wih[:,onehot] + bih
            int grow = (tid >> 4) * HID + bid * UPB + (tid & 15);
            float v = dec_bih[grow];
            if (prev_idx >= 0) v += __ldg(&dec_Wih[(size_t)grow * INSZ + prev_idx]);
            gi_s[tid] = v;
        }
        matvec48_h2(ws, hph2 + (j & 1) * (HID / 2), gh_s, bhh_s, tid);
        __syncthreads();                // gh_s + gi_s ready
        if (warp == 0) {
            if (tid < UPB) {
                float r = sigmoidf_(gi_s[tid]           + gh_s[tid]);
                float z = sigmoidf_(gi_s[UPB + tid]     + gh_s[UPB + tid]);
                float n = tanhf(    gi_s[2 * UPB + tid] + r * gh_s[2 * UPB + tid]);
                h_reg = (1.f - z) * n + z * h_reg;
            }
            publish_h(bid, tid, h_reg, base, j + 1);
        }
        exch_load_h(warp, lane, base, j + 1, hph2 + ((j + 1) & 1) * (HID / 2));
        j++;
        __syncthreads();                // h_new (fp16) in SMEM for logits

        // logits: 16 warps x 2 rows of fp16 W_out against SMEM h
        {
            const __half2* hp = hph2 + (j & 1) * (HID / 2);
            uint4 hreg[8];
#pragma unroll
            for (int c = 0; c < 8; c++)
                hreg[c] = *(const uint4*)(hp + (c * 32 + lane) * 4);
#pragma unroll
            for (int rr = 0; rr < 2; rr++) {
                int rl = warp * 2 + rr;
                int grow = bid * ORPB + rl;
                const uint4* wrow = (const uint4*)(g_Woh + (size_t)grow * HID);
                float acc = 0.f;
#pragma unroll
                for (int c = 0; c < 8; c++) {
                    uint4 w = __ldg(&wrow[lane + c * 32]);
                    __half2 sh = __hmul2(*(__half2*)&w.x, *(__half2*)&hreg[c].x);
                    sh = __hfma2(*(__half2*)&w.y, *(__half2*)&hreg[c].y, sh);
                    sh = __hfma2(*(__half2*)&w.z, *(__half2*)&hreg[c].z, sh);
                    sh = __hfma2(*(__half2*)&w.w, *(__half2*)&hreg[c].w, sh);
                    float2 f = __half22float2(sh);
                    acc += f.x + f.y;
                }
                acc = warp_sum(acc);
                if (lane == 0) ls[rl] = acc + b_out[grow];
            }
        }
        __syncthreads();                // ls ready

        // warp 0: local (max,argmax,sumexp) -> slot; poll all; reduce
        if (warp == 0) {
            float v = ls[lane];
            unsigned long long pack =
                ((unsigned long long)f2sortable(v) << 32) |
                (unsigned long long)(0xFFFFFFFFu - (unsigned)(bid * ORPB + lane));
#pragma unroll
            for (int o = 16; o; o >>= 1) {
                unsigned long long other = __shfl_xor_sync(0xffffffffu, pack, o);
                pack = other > pack ? other : pack;
            }
            float lmax = sortable2f((unsigned)(pack >> 32));
            float e = warp_sum(expf(v - lmax));
            unsigned s1 = s + 1;
            if (lane == 0) {
                ulonglong2 slot;
                slot.x = pack;
                slot.y = (unsigned long long)__float_as_uint(e);
                __stcg(&g_pdat[s1 & 1][bid], slot);
                fence_gpu();
                st_flag(&g_flag2p[bid * 8], base2 + s1);
            }
            // poll 4 flags per lane, load 4 slots, reduce
            {
                const unsigned* fp0 = &g_flag2p[lane * 8];
                const unsigned* fp1 = &g_flag2p[(lane + 32) * 8];
                const unsigned* fp2 = &g_flag2p[(lane + 64) * 8];
                const unsigned* fp3 = &g_flag2p[(lane + 96) * 8];
                while (ld_flag(fp0) - base2 < s1) { }
                while (ld_flag(fp1) - base2 < s1) { }
                while (ld_flag(fp2) - base2 < s1) { }
                while (ld_flag(fp3) - base2 < s1) { }
                fence_gpu();
                unsigned long long pk[4];
                float lsm[4];
#pragma unroll
                for (int i = 0; i < 4; i++) {
                    ulonglong2 sl = __ldcg(&g_pdat[s1 & 1][lane + i * 32]);
                    pk[i]  = sl.x;
                    lsm[i] = __uint_as_float((unsigned)sl.y);
                }
                unsigned long long m = pk[0];
#pragma unroll
                for (int i = 1; i < 4; i++) m = pk[i] > m ? pk[i] : m;
#pragma unroll
                for (int o = 16; o; o >>= 1) {
                    unsigned long long other = __shfl_xor_sync(0xffffffffu, m, o);
                    m = other > m ? other : m;
                }
                float gmax = sortable2f((unsigned)(m >> 32));
                float part = 0.f;
#pragma unroll
                for (int i = 0; i < 4; i++)
                    part += lsm[i] * expf(sortable2f((unsigned)(pk[i] >> 32)) - gmax);
                part = warp_sum(part);
                if (lane == 0) {
                    red_s[0] = gmax;
                    red_s[1] = logf(part);
                    red_s[2] = __uint_as_float(
                        0xFFFFFFFFu - (unsigned)(m & 0xFFFFFFFFull));
                }
            }
        }
        __syncthreads();                // red_s ready
        float gmax = red_s[0], lse = red_s[1];
        prev_idx = (int)__float_as_uint(red_s[2]);
        if (tid < ORPB)
            out[(size_t)s * OUTSZ + bid * ORPB + tid] = ls[tid] - gmax - lse;
    }
}

// ---------------- launch ----------------------------------------------------
extern "C" void kernel_launch(void* const* d_in, const int* in_sizes, int n_in,
                              void* d_out, int out_size) {
    const float* input   = (const float*)d_in[0];
    const float* enc_Wih = (const float*)d_in[1];
    const float* enc_Whh = (const float*)d_in[2];
    const float* enc_bih = (const float*)d_in[3];
    const float* enc_bhh = (const float*)d_in[4];
    const float* dec_Wih = (const float*)d_in[5];
    const float* dec_Whh = (const float*)d_in[6];
    const float* dec_bih = (const float*)d_in[7];
    const float* dec_bhh = (const float*)d_in[8];
    const float* W_out   = (const float*)d_in[9];
    const float* b_out   = (const float*)d_in[10];
    float* out = (float*)d_out;

    static const int kDynSmem = RPB * HID * sizeof(__half)   // weights 192KB
                              + HID * 2 * sizeof(__half);    // h double-buf 8KB
    cudaFuncSetAttribute(rnn_kernel,
                         cudaFuncAttributeMaxDynamicSharedMemorySize, kDynSmem);

    conv_x_kernel<<<(SEQ * INSZ / 4 + 255) / 256, 256>>>(input);
    conv_w_kernel<<<(G3 * INSZ / 4 + 255) / 256, 256>>>(enc_Wih);
    conv_wout_kernel<<<(OUTSZ * HID / 4 + 255) / 256, 256>>>(W_out);

    dim3 g1(G3 / 128, SEQ / 128);   // 48 x 4
    gemm_wmma_kernel<<<g1, 256>>>();

    rnn_kernel<<<NB, NT, kDynSmem>>>(enc_Whh, enc_bih, enc_bhh,
                                     dec_Wih, dec_Whh, dec_bih, dec_bhh,
                                     b_out, out);
}